// round 15
// baseline (speedup 1.0000x reference)
#include <cuda_runtime.h>
#include <cuda_bf16.h>
#include <cuda_fp16.h>
#include <stdint.h>

#define B_ 8
#define C_ 128
#define N_ 4096

// ---------------------------------------------------------------------------
// Scratch.
// g_wh/g_wl : weights bf16 hi/lo [4][128][128]
// g_qh/g_kh/g_vh : Q (QSCALE folded), K, V single fp16 [B][N][C]
// g_oh/g_ol : attention output bf16 hi/lo [B][N][C]
// ---------------------------------------------------------------------------
__device__ __nv_bfloat16 g_wh[4*C_*C_];
__device__ __nv_bfloat16 g_wl[4*C_*C_];
__device__ __half        g_qh[B_*N_*C_];
__device__ __half        g_kh[B_*N_*C_];
__device__ __half        g_vh[B_*N_*C_];
__device__ __nv_bfloat16 g_oh[B_*N_*C_];
__device__ __nv_bfloat16 g_ol[B_*N_*C_];

#define QSCALE (0.08838834764831845f * 1.4426950408889634f)

// ---------------------------------------------------------------------------
// PTX helpers
// ---------------------------------------------------------------------------
__device__ __forceinline__ uint32_t smem_u32(const void* p) {
    uint32_t a;
    asm("{ .reg .u64 t; cvta.to.shared.u64 t, %1; cvt.u32.u64 %0, t; }" : "=r"(a) : "l"(p));
    return a;
}
__device__ __forceinline__ void ldsm4(uint32_t* r, uint32_t a) {
    asm volatile("ldmatrix.sync.aligned.m8n8.x4.shared.b16 {%0,%1,%2,%3}, [%4];"
        : "=r"(r[0]), "=r"(r[1]), "=r"(r[2]), "=r"(r[3]) : "r"(a));
}
__device__ __forceinline__ void ldsm4t(uint32_t* r, uint32_t a) {
    asm volatile("ldmatrix.sync.aligned.m8n8.x4.trans.shared.b16 {%0,%1,%2,%3}, [%4];"
        : "=r"(r[0]), "=r"(r[1]), "=r"(r[2]), "=r"(r[3]) : "r"(a));
}
__device__ __forceinline__ void mma16816(float* c, const uint32_t* a,
                                         uint32_t b0, uint32_t b1) {
    asm volatile("mma.sync.aligned.m16n8k16.row.col.f32.bf16.bf16.f32 "
        "{%0,%1,%2,%3}, {%4,%5,%6,%7}, {%8,%9}, {%0,%1,%2,%3};"
        : "+f"(c[0]), "+f"(c[1]), "+f"(c[2]), "+f"(c[3])
        : "r"(a[0]), "r"(a[1]), "r"(a[2]), "r"(a[3]), "r"(b0), "r"(b1));
}
__device__ __forceinline__ void mma16816h(float* c, const uint32_t* a,
                                          uint32_t b0, uint32_t b1) {
    asm volatile("mma.sync.aligned.m16n8k16.row.col.f32.f16.f16.f32 "
        "{%0,%1,%2,%3}, {%4,%5,%6,%7}, {%8,%9}, {%0,%1,%2,%3};"
        : "+f"(c[0]), "+f"(c[1]), "+f"(c[2]), "+f"(c[3])
        : "r"(a[0]), "r"(a[1]), "r"(a[2]), "r"(a[3]), "r"(b0), "r"(b1));
}
__device__ __forceinline__ uint32_t packbf(float lo, float hi) {
    uint32_t r;
    asm("cvt.rn.bf16x2.f32 %0, %1, %2;" : "=r"(r) : "f"(hi), "f"(lo));
    return r;
}
__device__ __forceinline__ uint32_t packhf(float lo, float hi) {
    uint32_t r;
    asm("cvt.rn.f16x2.f32 %0, %1, %2;" : "=r"(r) : "f"(hi), "f"(lo));
    return r;
}
__device__ __forceinline__ uint32_t packres(float v0, float v1, uint32_t h) {
    float h0 = __uint_as_float(h << 16);
    float h1 = __uint_as_float(h & 0xffff0000u);
    return packbf(v0 - h0, v1 - h1);
}
__device__ __forceinline__ float ex2f(float x) {
    float y; asm("ex2.approx.ftz.f32 %0, %1;" : "=f"(y) : "f"(x)); return y;
}
#define CP_ASYNC16(d, g) \
    asm volatile("cp.async.cg.shared.global [%0], [%1], 16;" :: "r"(d), "l"(g) : "memory")
#define CP_COMMIT()  asm volatile("cp.async.commit_group;" ::: "memory")
#define CP_WAIT1()   asm volatile("cp.async.wait_group 1;" ::: "memory")
#define CP_WAIT0()   asm volatile("cp.async.wait_group 0;" ::: "memory")

#define KROW 272

// ---------------------------------------------------------------------------
// convert_w: wq/wk/wv/wo fp32 -> bf16 hi/lo. Grid 32 (8 chunks per matrix).
// ---------------------------------------------------------------------------
__global__ __launch_bounds__(256) void convert_w_kernel(
    const float* __restrict__ wq, const float* __restrict__ wk,
    const float* __restrict__ wv, const float* __restrict__ wo)
{
    const float* src[4] = {wq, wk, wv, wo};
    const int m = blockIdx.x >> 3;
    const int ch = blockIdx.x & 7;
    const float* s = src[m] + ch * (C_*C_/8);
    __nv_bfloat16* dh = g_wh + m*C_*C_ + ch*(C_*C_/8);
    __nv_bfloat16* dl = g_wl + m*C_*C_ + ch*(C_*C_/8);
    for (int e = threadIdx.x; e < C_*C_/16; e += 256) {
        float v0 = s[2*e], v1 = s[2*e+1];
        uint32_t h = packbf(v0, v1);
        *(uint32_t*)(dh + 2*e) = h;
        *(uint32_t*)(dl + 2*e) = packres(v0, v1, h);
    }
}

// ---------------------------------------------------------------------------
// gemm_qkv (convert_x fused, 64-token tiles, 2 CTAs/SM):
// reads fp32 X [B][C][N], fw-scales, transposes, splits bf16 hi/lo in smem,
// then 3-term bf16 mma XW^T + b for q,k,v. W single-buffered, staged serially
// per projection (co-resident CTA hides the staging latency).
// Warp w: tokens (w&3)*16, channels (w>>2)*64.
// SMEM: Xh 0 (64x272=17408), Xl 17408; Wh 34816 (128x272), Wl 69632 -> 104448.
// fp32 staging [128c][68n] = 34816 B reuses the W region during the prologue.
// ---------------------------------------------------------------------------
#define GQ_XL 17408
#define GQ_W  34816
#define GQ_WL 69632
#define GQ_SMEM 104448

__global__ __launch_bounds__(256, 2) void gemm_qkv_kernel(
    const float* __restrict__ X, const float* __restrict__ fw,
    const float* __restrict__ bq, const float* __restrict__ bk,
    const float* __restrict__ bv)
{
    extern __shared__ char sm[];
    const uint32_t sb = smem_u32(sm);
    const int tid  = threadIdx.x;
    const int lane = tid & 31;
    const int w    = tid >> 5;
    const int b    = blockIdx.y;
    const int nt   = blockIdx.x * 64;
    const int lm8  = lane & 7;
    const int t8   = lane >> 3;

    // ---- fused convert_x: fp32 stage -> transpose -> bf16 hi/lo ----
    {
        float* xs = (float*)(sm + GQ_W);      // [c][n] 128x68 fp32 staging
        for (int e = tid; e < C_*64; e += 256) {
            int c = e >> 6, n = e & 63;
            xs[c*68 + n] = X[((size_t)b*C_ + c)*N_ + nt + n] * fw[c];
        }
        __syncthreads();
        for (int e = tid; e < 4096; e += 256) {      // 64 tok x 64 c-pairs
            int n = e >> 6, c2 = e & 63;
            float v0 = xs[(2*c2  )*68 + n];
            float v1 = xs[(2*c2+1)*68 + n];
            uint32_t h = packbf(v0, v1);
            *(uint32_t*)(sm +         n*KROW + c2*4) = h;
            *(uint32_t*)(sm + GQ_XL + n*KROW + c2*4) = packres(v0, v1, h);
        }
        __syncthreads();                      // staging region free for W
    }

    const int tr0 = (w & 3) * 16;             // token group
    const int cc0 = (w >> 2) * 64;            // channel half
    const uint32_t a_addr = sb + (tr0 + (t8&1)*8 + lm8)*KROW + (t8>>1)*16;
    const uint32_t b_off  = ((t8>>1)*8 + lm8)*KROW + (t8&1)*16;
    const int r0 = tr0 + (lane >> 2);
    const int qr = lane & 3;

    // hoist A fragments once (shared across the three projections)
    uint32_t aH[8][4], aL[8][4];
    #pragma unroll
    for (int ks = 0; ks < 8; ks++) {
        ldsm4(aH[ks], a_addr + ks*32);
        ldsm4(aL[ks], a_addr + GQ_XL + ks*32);
    }

    const float* Bp[3] = {bq, bk, bv};

    for (int p = 0; p < 3; p++) {
        // stage Wp (single buffer; serial, latency hidden by co-resident CTA)
        {
            const __nv_bfloat16* sh = g_wh + p*C_*C_;
            const __nv_bfloat16* sl = g_wl + p*C_*C_;
            #pragma unroll
            for (int j = 0; j < 8; j++) {
                int idx = tid + j*256;        // 128 rows x 16 chunks
                int r = idx >> 4, c = idx & 15;
                CP_ASYNC16(sb + GQ_W  + r*KROW + c*16, sh + r*C_ + c*8);
                CP_ASYNC16(sb + GQ_WL + r*KROW + c*16, sl + r*C_ + c*8);
            }
            CP_COMMIT();
        }
        CP_WAIT0();
        __syncthreads();

        const float* bias = Bp[p];
        __half* dst = (p == 0) ? g_qh : ((p == 1) ? g_kh : g_vh);
        const float sc = (p == 0) ? QSCALE : 1.0f;

        #pragma unroll
        for (int np = 0; np < 4; np++) {
            float acc[2][4];
            #pragma unroll
            for (int f = 0; f < 2; f++)
                { acc[f][0]=0.f; acc[f][1]=0.f; acc[f][2]=0.f; acc[f][3]=0.f; }
            #pragma unroll
            for (int ks = 0; ks < 8; ks++) {
                uint32_t bh[4], bl[4];
                uint32_t ba = b_off + (cc0 + np*16)*KROW + ks*32;
                ldsm4(bh, sb + GQ_W  + ba);
                ldsm4(bl, sb + GQ_WL + ba);
                mma16816(acc[0], aH[ks], bh[0], bh[1]);
                mma16816(acc[0], aH[ks], bl[0], bl[1]);
                mma16816(acc[0], aL[ks], bh[0], bh[1]);
                mma16816(acc[1], aH[ks], bh[2], bh[3]);
                mma16816(acc[1], aH[ks], bl[2], bl[3]);
                mma16816(acc[1], aL[ks], bh[2], bh[3]);
            }
            #pragma unroll
            for (int f = 0; f < 2; f++) {
                int ch = cc0 + (2*np + f)*8 + qr*2;
                float b0 = __ldg(&bias[ch]), b1 = __ldg(&bias[ch+1]);
                float v0 = (acc[f][0] + b0)*sc, v1 = (acc[f][1] + b1)*sc;
                float v2 = (acc[f][2] + b0)*sc, v3 = (acc[f][3] + b1)*sc;
                size_t o0 = ((size_t)b*N_ + nt + r0    )*C_ + ch;
                size_t o1 = ((size_t)b*N_ + nt + r0 + 8)*C_ + ch;
                *(uint32_t*)(dst + o0) = packhf(v0, v1);
                *(uint32_t*)(dst + o1) = packhf(v2, v3);
            }
        }
        if (p < 2) __syncthreads();           // all warps done reading W
    }
}

// ---------------------------------------------------------------------------
// fp16 mma flash attention (R12 configuration — frozen): S = Qh*Kh; O += Ph*Vh.
// 256 threads, 128 queries/CTA, 64-key double-buffered KV, 2 CTAs/SM.
// SMEM: Qh 0 (34816); stages at 34816 + s*34816 (Kh +0, Vh +17408).
// ---------------------------------------------------------------------------
#define SM_KV  34816
#define STAGE  34816
#define ATTN_SMEM 104448

__device__ __forceinline__ void kv_prefetch(uint32_t dstb, int tid,
    const __half* kh, const __half* vh, int n0)
{
    #pragma unroll
    for (int j = 0; j < 4; j++) {
        int idx = tid + j*256;
        int r = idx >> 4, c = idx & 15;
        CP_ASYNC16(dstb +         r*KROW + c*16, kh + (size_t)(n0 + r)*C_ + c*8);
        CP_ASYNC16(dstb + 17408 + r*KROW + c*16, vh + (size_t)(n0 + r)*C_ + c*8);
    }
}

__global__ __launch_bounds__(256, 2) void attn_mma_kernel()
{
    extern __shared__ char sm[];
    const uint32_t sb = smem_u32(sm);
    const int tid  = threadIdx.x;
    const int lane = tid & 31;
    const int w    = tid >> 5;
    const int b    = blockIdx.y;
    const int q0   = blockIdx.x * 128;
    const int lm8  = lane & 7;
    const int t8   = lane >> 3;

    const __half* qh_b = g_qh + ((size_t)b*N_ + q0)*C_;
    const __half* kh_b = g_kh + (size_t)b*N_*C_;
    const __half* vh_b = g_vh + (size_t)b*N_*C_;

    #pragma unroll
    for (int j = 0; j < 8; j++) {
        int idx = tid + j*256;
        int r = idx >> 4, c = idx & 15;
        CP_ASYNC16(sb + r*KROW + c*16, qh_b + (size_t)r*C_ + c*8);
    }
    kv_prefetch(sb + SM_KV, tid, kh_b, vh_b, 0);
    CP_COMMIT();

    const uint32_t q_addr = sb + (w*16 + (t8&1)*8 + lm8)*KROW + (t8>>1)*16;
    const uint32_t k_off  = ((t8>>1)*8 + lm8)*KROW + (t8&1)*16;
    const uint32_t v_off  = ((t8&1)*8 + lm8)*KROW + (t8>>1)*16;

    float o[16][4];
    #pragma unroll
    for (int f = 0; f < 16; f++) { o[f][0]=0.f; o[f][1]=0.f; o[f][2]=0.f; o[f][3]=0.f; }
    float l0 = 0.f, l1 = 0.f;

    for (int kt = 0; kt < N_/64; kt++) {
        CP_WAIT0();
        __syncthreads();
        if (kt < N_/64 - 1) {
            kv_prefetch(sb + SM_KV + ((kt+1)&1)*STAGE, tid,
                        kh_b, vh_b, (kt+1)*64);
            CP_COMMIT();
        }

        const uint32_t base = sb + SM_KV + (kt&1)*STAGE;
        const uint32_t kbh = base, vbh = base + 17408;

        float s[8][4];
        #pragma unroll
        for (int f = 0; f < 8; f++) { s[f][0]=0.f; s[f][1]=0.f; s[f][2]=0.f; s[f][3]=0.f; }

        #pragma unroll
        for (int ks = 0; ks < 8; ks++) {
            uint32_t qf[4];
            ldsm4(qf, q_addr + ks*32);
            #pragma unroll
            for (int np = 0; np < 4; np++) {
                uint32_t bh[4];
                ldsm4(bh, kbh + k_off + np*16*KROW + ks*32);
                mma16816h(s[2*np],   qf, bh[0], bh[1]);
                mma16816h(s[2*np+1], qf, bh[2], bh[3]);
            }
        }

        #pragma unroll
        for (int ks4 = 0; ks4 < 4; ks4++) {
            uint32_t ah[4];
            #pragma unroll
            for (int fi = 0; fi < 2; fi++) {
                float* sf = s[2*ks4 + fi];
                float e0 = ex2f(sf[0]), e1 = ex2f(sf[1]);
                float e2 = ex2f(sf[2]), e3 = ex2f(sf[3]);
                l0 += e0 + e1;  l1 += e2 + e3;
                ah[fi*2+0] = packhf(e0, e1);
                ah[fi*2+1] = packhf(e2, e3);
            }
            #pragma unroll
            for (int nd = 0; nd < 8; nd++) {
                uint32_t vh[4];
                ldsm4t(vh, vbh + v_off + ks4*16*KROW + nd*32);
                mma16816h(o[2*nd],   ah, vh[0], vh[1]);
                mma16816h(o[2*nd+1], ah, vh[2], vh[3]);
            }
        }
    }

    l0 += __shfl_xor_sync(0xffffffffu, l0, 1);
    l0 += __shfl_xor_sync(0xffffffffu, l0, 2);
    l1 += __shfl_xor_sync(0xffffffffu, l1, 1);
    l1 += __shfl_xor_sync(0xffffffffu, l1, 2);
    const float inv0 = 1.0f / l0, inv1 = 1.0f / l1;

    const int r0 = w*16 + (lane >> 2);
    const int qr = lane & 3;
    #pragma unroll
    for (int nd = 0; nd < 16; nd++) {
        int ch = nd*8 + qr*2;
        float v0 = o[nd][0]*inv0, v1 = o[nd][1]*inv0;
        float v2 = o[nd][2]*inv1, v3 = o[nd][3]*inv1;
        size_t o0 = ((size_t)b*N_ + q0 + r0    )*C_ + ch;
        size_t o1 = ((size_t)b*N_ + q0 + r0 + 8)*C_ + ch;
        uint32_t h01 = packbf(v0, v1), h23 = packbf(v2, v3);
        *(uint32_t*)(g_oh + o0) = h01;
        *(uint32_t*)(g_ol + o0) = packres(v0, v1, h01);
        *(uint32_t*)(g_oh + o1) = h23;
        *(uint32_t*)(g_ol + o1) = packres(v2, v3, h23);
    }
}

// ---------------------------------------------------------------------------
// gemm_out: out[B][C][N] = O(bf16 hi/lo)*Wo^T + bo, 3-term bf16 mma.
// 64-token tiles, 2 CTAs/SM (R14 configuration — frozen).
// ---------------------------------------------------------------------------
#define GO_OL 17408
#define GO_W  34816
#define GO_SMEM 104448

__global__ __launch_bounds__(256, 2) void gemm_out_kernel(
    const float* __restrict__ bo, float* __restrict__ out)
{
    extern __shared__ char sm[];
    const uint32_t sb = smem_u32(sm);
    const int tid  = threadIdx.x;
    const int lane = tid & 31;
    const int w    = tid >> 5;
    const int b    = blockIdx.y;
    const int nt   = blockIdx.x * 64;
    const int lm8  = lane & 7;
    const int t8   = lane >> 3;

    {
        const __nv_bfloat16* oh = g_oh + ((size_t)b*N_ + nt)*C_;
        const __nv_bfloat16* ol = g_ol + ((size_t)b*N_ + nt)*C_;
        const __nv_bfloat16* wh = g_wh + 3*C_*C_;
        const __nv_bfloat16* wl = g_wl + 3*C_*C_;
        #pragma unroll
        for (int j = 0; j < 4; j++) {
            int idx = tid + j*256;
            int r = idx >> 4, c = idx & 15;
            CP_ASYNC16(sb +         r*KROW + c*16, oh + (size_t)r*C_ + c*8);
            CP_ASYNC16(sb + GO_OL + r*KROW + c*16, ol + (size_t)r*C_ + c*8);
        }
        #pragma unroll
        for (int j = 0; j < 8; j++) {
            int idx = tid + j*256;
            int r = idx >> 4, c = idx & 15;
            CP_ASYNC16(sb + GO_W +         r*KROW + c*16, wh + r*C_ + c*8);
            CP_ASYNC16(sb + GO_W + GO_W  + r*KROW + c*16, wl + r*C_ + c*8);
        }
        CP_COMMIT();
    }
    CP_WAIT0();
    __syncthreads();

    const int tr0 = (w & 3) * 16;
    const int cc0 = (w >> 2) * 64;
    const uint32_t a_addr = sb + (tr0 + (t8&1)*8 + lm8)*KROW + (t8>>1)*16;
    const uint32_t b_off  = ((t8>>1)*8 + lm8)*KROW + (t8&1)*16;
    const int r0 = tr0 + (lane >> 2);
    const int qr = lane & 3;

    uint32_t aH[8][4], aL[8][4];
    #pragma unroll
    for (int ks = 0; ks < 8; ks++) {
        ldsm4(aH[ks], a_addr + ks*32);
        ldsm4(aL[ks], a_addr + GO_OL + ks*32);
    }
    __syncthreads();

    float* smT = (float*)sm;                 // [128 ch][68 tok]
    #pragma unroll
    for (int np = 0; np < 4; np++) {
        float acc[2][4];
        #pragma unroll
        for (int f = 0; f < 2; f++)
            { acc[f][0]=0.f; acc[f][1]=0.f; acc[f][2]=0.f; acc[f][3]=0.f; }
        #pragma unroll
        for (int ks = 0; ks < 8; ks++) {
            uint32_t bh[4], bl[4];
            uint32_t ba = b_off + (cc0 + np*16)*KROW + ks*32;
            ldsm4(bh, sb + GO_W + ba);
            ldsm4(bl, sb + GO_W + GO_W + ba);
            mma16816(acc[0], aH[ks], bh[0], bh[1]);
            mma16816(acc[0], aH[ks], bl[0], bl[1]);
            mma16816(acc[0], aL[ks], bh[0], bh[1]);
            mma16816(acc[1], aH[ks], bh[2], bh[3]);
            mma16816(acc[1], aH[ks], bl[2], bl[3]);
            mma16816(acc[1], aL[ks], bh[2], bh[3]);
        }
        #pragma unroll
        for (int f = 0; f < 2; f++) {
            int ch = cc0 + (2*np + f)*8 + qr*2;
            float b0 = __ldg(&bo[ch]), b1 = __ldg(&bo[ch+1]);
            smT[(ch  )*68 + r0    ] = acc[f][0] + b0;
            smT[(ch+1)*68 + r0    ] = acc[f][1] + b1;
            smT[(ch  )*68 + r0 + 8] = acc[f][2] + b0;
            smT[(ch+1)*68 + r0 + 8] = acc[f][3] + b1;
        }
    }
    __syncthreads();

    for (int e = tid; e < 2048; e += 256) {
        int ch = e >> 4, t4 = e & 15;
        float4 v = *(float4*)&smT[ch*68 + t4*4];
        *(float4*)(out + ((size_t)b*C_ + ch)*N_ + nt + t4*4) = v;
    }
}

// ---------------------------------------------------------------------------
extern "C" void kernel_launch(void* const* d_in, const int* in_sizes, int n_in,
                              void* d_out, int out_size)
{
    const float* x  = (const float*)d_in[0];
    const float* fw = (const float*)d_in[1];
    const float* wq = (const float*)d_in[2];
    const float* bq = (const float*)d_in[3];
    const float* wk = (const float*)d_in[4];
    const float* bk = (const float*)d_in[5];
    const float* wv = (const float*)d_in[6];
    const float* bv = (const float*)d_in[7];
    const float* wo = (const float*)d_in[8];
    const float* bo = (const float*)d_in[9];
    float* out = (float*)d_out;

    cudaFuncSetAttribute(gemm_qkv_kernel, cudaFuncAttributeMaxDynamicSharedMemorySize, GQ_SMEM);
    cudaFuncSetAttribute(attn_mma_kernel, cudaFuncAttributeMaxDynamicSharedMemorySize, ATTN_SMEM);
    cudaFuncSetAttribute(gemm_out_kernel, cudaFuncAttributeMaxDynamicSharedMemorySize, GO_SMEM);

    convert_w_kernel<<<32, 256>>>(wq, wk, wv, wo);
    dim3 qg(N_/64, B_);
    gemm_qkv_kernel<<<qg, 256, GQ_SMEM>>>(x, fw, bq, bk, bv);
    dim3 ag(N_/128, B_);
    attn_mma_kernel<<<ag, 256, ATTN_SMEM>>>();
    dim3 og(N_/64, B_);
    gemm_out_kernel<<<og, 256, GO_SMEM>>>(bo, out);
}

// round 16
// speedup vs baseline: 1.5387x; 1.5387x over previous
#include <cuda_runtime.h>
#include <cuda_bf16.h>
#include <cuda_fp16.h>
#include <stdint.h>

#define B_ 8
#define C_ 128
#define N_ 4096

// ---------------------------------------------------------------------------
// Scratch.
// g_wh/g_wl : weights bf16 hi/lo [4][128][128]
// g_qh/g_kh/g_vh : Q (QSCALE folded), K, V single fp16 [B][N][C]
// g_oh/g_ol : attention output bf16 hi/lo [B][N][C]
// ---------------------------------------------------------------------------
__device__ __nv_bfloat16 g_wh[4*C_*C_];
__device__ __nv_bfloat16 g_wl[4*C_*C_];
__device__ __half        g_qh[B_*N_*C_];
__device__ __half        g_kh[B_*N_*C_];
__device__ __half        g_vh[B_*N_*C_];
__device__ __nv_bfloat16 g_oh[B_*N_*C_];
__device__ __nv_bfloat16 g_ol[B_*N_*C_];

#define QSCALE (0.08838834764831845f * 1.4426950408889634f)

// ---------------------------------------------------------------------------
// PTX helpers
// ---------------------------------------------------------------------------
__device__ __forceinline__ uint32_t smem_u32(const void* p) {
    uint32_t a;
    asm("{ .reg .u64 t; cvta.to.shared.u64 t, %1; cvt.u32.u64 %0, t; }" : "=r"(a) : "l"(p));
    return a;
}
__device__ __forceinline__ void ldsm4(uint32_t* r, uint32_t a) {
    asm volatile("ldmatrix.sync.aligned.m8n8.x4.shared.b16 {%0,%1,%2,%3}, [%4];"
        : "=r"(r[0]), "=r"(r[1]), "=r"(r[2]), "=r"(r[3]) : "r"(a));
}
__device__ __forceinline__ void ldsm4t(uint32_t* r, uint32_t a) {
    asm volatile("ldmatrix.sync.aligned.m8n8.x4.trans.shared.b16 {%0,%1,%2,%3}, [%4];"
        : "=r"(r[0]), "=r"(r[1]), "=r"(r[2]), "=r"(r[3]) : "r"(a));
}
__device__ __forceinline__ void mma16816(float* c, const uint32_t* a,
                                         uint32_t b0, uint32_t b1) {
    asm volatile("mma.sync.aligned.m16n8k16.row.col.f32.bf16.bf16.f32 "
        "{%0,%1,%2,%3}, {%4,%5,%6,%7}, {%8,%9}, {%0,%1,%2,%3};"
        : "+f"(c[0]), "+f"(c[1]), "+f"(c[2]), "+f"(c[3])
        : "r"(a[0]), "r"(a[1]), "r"(a[2]), "r"(a[3]), "r"(b0), "r"(b1));
}
__device__ __forceinline__ void mma16816h(float* c, const uint32_t* a,
                                          uint32_t b0, uint32_t b1) {
    asm volatile("mma.sync.aligned.m16n8k16.row.col.f32.f16.f16.f32 "
        "{%0,%1,%2,%3}, {%4,%5,%6,%7}, {%8,%9}, {%0,%1,%2,%3};"
        : "+f"(c[0]), "+f"(c[1]), "+f"(c[2]), "+f"(c[3])
        : "r"(a[0]), "r"(a[1]), "r"(a[2]), "r"(a[3]), "r"(b0), "r"(b1));
}
__device__ __forceinline__ uint32_t packbf(float lo, float hi) {
    uint32_t r;
    asm("cvt.rn.bf16x2.f32 %0, %1, %2;" : "=r"(r) : "f"(hi), "f"(lo));
    return r;
}
__device__ __forceinline__ uint32_t packhf(float lo, float hi) {
    uint32_t r;
    asm("cvt.rn.f16x2.f32 %0, %1, %2;" : "=r"(r) : "f"(hi), "f"(lo));
    return r;
}
__device__ __forceinline__ uint32_t packres(float v0, float v1, uint32_t h) {
    float h0 = __uint_as_float(h << 16);
    float h1 = __uint_as_float(h & 0xffff0000u);
    return packbf(v0 - h0, v1 - h1);
}
__device__ __forceinline__ float ex2f(float x) {
    float y; asm("ex2.approx.ftz.f32 %0, %1;" : "=f"(y) : "f"(x)); return y;
}
#define CP_ASYNC16(d, g) \
    asm volatile("cp.async.cg.shared.global [%0], [%1], 16;" :: "r"(d), "l"(g) : "memory")
#define CP_COMMIT()  asm volatile("cp.async.commit_group;" ::: "memory")
#define CP_WAIT1()   asm volatile("cp.async.wait_group 1;" ::: "memory")
#define CP_WAIT0()   asm volatile("cp.async.wait_group 0;" ::: "memory")

#define KROW 272

// ---------------------------------------------------------------------------
// convert_w: wq/wk/wv/wo fp32 -> bf16 hi/lo. Grid 32 (8 chunks per matrix).
// ---------------------------------------------------------------------------
__global__ __launch_bounds__(256) void convert_w_kernel(
    const float* __restrict__ wq, const float* __restrict__ wk,
    const float* __restrict__ wv, const float* __restrict__ wo)
{
    const float* src[4] = {wq, wk, wv, wo};
    const int m = blockIdx.x >> 3;
    const int ch = blockIdx.x & 7;
    const float* s = src[m] + ch * (C_*C_/8);
    __nv_bfloat16* dh = g_wh + m*C_*C_ + ch*(C_*C_/8);
    __nv_bfloat16* dl = g_wl + m*C_*C_ + ch*(C_*C_/8);
    for (int e = threadIdx.x; e < C_*C_/16; e += 256) {
        float v0 = s[2*e], v1 = s[2*e+1];
        uint32_t h = packbf(v0, v1);
        *(uint32_t*)(dh + 2*e) = h;
        *(uint32_t*)(dl + 2*e) = packres(v0, v1, h);
    }
}

// ---------------------------------------------------------------------------
// gemm_qkv (convert_x fused, R14 double-buffered W pipeline + early W0 prefetch):
// W0 -> buf1 issued BEFORE the convert (buf1 idle during staging); fp32 X
// staging occupies buf0; after the convert frees buf0, W1 -> buf0.
// p=0 reads buf1, p=1 reads buf0, p=2 reads buf1 (restaged).
// SMEM: Xh 0, Xl 34816; W buf0 at 69632, buf1 at 139264 (Wh +0, Wl +34816).
// ---------------------------------------------------------------------------
#define GQ_XL 34816
#define GQ_W  69632
#define GQ_WS 69632
#define GQ_SMEM 208896

__device__ __forceinline__ void stage_w_async(uint32_t dst, int tid, int p) {
    const __nv_bfloat16* sh = g_wh + p*C_*C_;
    const __nv_bfloat16* sl = g_wl + p*C_*C_;
    #pragma unroll
    for (int j = 0; j < 8; j++) {
        int idx = tid + j*256;
        int r = idx >> 4, c = idx & 15;
        CP_ASYNC16(dst +         r*KROW + c*16, sh + r*C_ + c*8);
        CP_ASYNC16(dst + GQ_XL + r*KROW + c*16, sl + r*C_ + c*8);
    }
}

__global__ __launch_bounds__(256, 1) void gemm_qkv_kernel(
    const float* __restrict__ X, const float* __restrict__ fw,
    const float* __restrict__ bq, const float* __restrict__ bk,
    const float* __restrict__ bv)
{
    extern __shared__ char sm[];
    const uint32_t sb = smem_u32(sm);
    const int tid  = threadIdx.x;
    const int lane = tid & 31;
    const int w    = tid >> 5;
    const int b    = blockIdx.y;
    const int nt   = blockIdx.x * 128;
    const int lm8  = lane & 7;
    const int t8   = lane >> 3;

    // early prefetch: W0 -> buf1 (group A), overlaps with convert_x below
    stage_w_async(sb + GQ_W + GQ_WS, tid, 0);
    CP_COMMIT();

    // ---- fused convert_x: fp32 stage (buf0 region) -> transpose -> bf16 hi/lo
    {
        float* xs = (float*)(sm + GQ_W);      // [c][n] 128x132 fp32 staging
        for (int e = tid; e < C_*128; e += 256) {
            int c = e >> 7, n = e & 127;
            xs[c*132 + n] = X[((size_t)b*C_ + c)*N_ + nt + n] * fw[c];
        }
        __syncthreads();
        for (int e = tid; e < 8192; e += 256) {
            int n = e >> 6, c2 = e & 63;
            float v0 = xs[(2*c2  )*132 + n];
            float v1 = xs[(2*c2+1)*132 + n];
            uint32_t h = packbf(v0, v1);
            *(uint32_t*)(sm +         n*KROW + c2*4) = h;
            *(uint32_t*)(sm + GQ_XL + n*KROW + c2*4) = packres(v0, v1, h);
        }
        __syncthreads();                      // buf0 free for W1
    }

    // W1 -> buf0 (group B)
    stage_w_async(sb + GQ_W, tid, 1);
    CP_COMMIT();
    CP_WAIT1();                               // W0 (group A) resident
    __syncthreads();

    const uint32_t a_addr = sb + (w*16 + (t8&1)*8 + lm8)*KROW + (t8>>1)*16;
    const uint32_t b_off  = ((t8>>1)*8 + lm8)*KROW + (t8&1)*16;
    const int r0 = w*16 + (lane >> 2);
    const int qr = lane & 3;

    uint32_t aH[8][4], aL[8][4];
    #pragma unroll
    for (int ks = 0; ks < 8; ks++) {
        ldsm4(aH[ks], a_addr + ks*32);
        ldsm4(aL[ks], a_addr + GQ_XL + ks*32);
    }

    const float* Bp[3] = {bq, bk, bv};

    for (int p = 0; p < 3; p++) {
        // p=0: buf1 (W0);  p=1: buf0 (W1);  p=2: buf1 (W2 restaged)
        const uint32_t wb = sb + GQ_W + ((p & 1) ^ 1) * GQ_WS;
        const float* bias = Bp[p];
        __half* dst = (p == 0) ? g_qh : ((p == 1) ? g_kh : g_vh);
        const float sc = (p == 0) ? QSCALE : 1.0f;
        #pragma unroll
        for (int np = 0; np < 8; np++) {
            float acc[2][4];
            #pragma unroll
            for (int f = 0; f < 2; f++)
                { acc[f][0]=0.f; acc[f][1]=0.f; acc[f][2]=0.f; acc[f][3]=0.f; }
            #pragma unroll
            for (int ks = 0; ks < 8; ks++) {
                uint32_t bh[4], bl[4];
                uint32_t ba = b_off + np*16*KROW + ks*32;
                ldsm4(bh, wb + ba);
                ldsm4(bl, wb + GQ_XL + ba);
                mma16816(acc[0], aH[ks], bh[0], bh[1]);
                mma16816(acc[0], aH[ks], bl[0], bl[1]);
                mma16816(acc[0], aL[ks], bh[0], bh[1]);
                mma16816(acc[1], aH[ks], bh[2], bh[3]);
                mma16816(acc[1], aH[ks], bl[2], bl[3]);
                mma16816(acc[1], aL[ks], bh[2], bh[3]);
            }
            #pragma unroll
            for (int f = 0; f < 2; f++) {
                int ch = (2*np + f)*8 + qr*2;
                float b0 = __ldg(&bias[ch]), b1 = __ldg(&bias[ch+1]);
                float v0 = (acc[f][0] + b0)*sc, v1 = (acc[f][1] + b1)*sc;
                float v2 = (acc[f][2] + b0)*sc, v3 = (acc[f][3] + b1)*sc;
                size_t o0 = ((size_t)b*N_ + nt + r0    )*C_ + ch;
                size_t o1 = ((size_t)b*N_ + nt + r0 + 8)*C_ + ch;
                *(uint32_t*)(dst + o0) = packhf(v0, v1);
                *(uint32_t*)(dst + o1) = packhf(v2, v3);
            }
        }
        if (p == 0) {
            __syncthreads();                  // all warps done reading buf1
            stage_w_async(sb + GQ_W + GQ_WS, tid, 2);   // W2 -> buf1 (group C)
            CP_COMMIT();
            CP_WAIT1();                       // W1 (group B) resident
            __syncthreads();
        } else if (p == 1) {
            CP_WAIT0();                       // W2 resident
            __syncthreads();
        }
    }
}

// ---------------------------------------------------------------------------
// fp16 mma flash attention (R12 configuration — frozen): S = Qh*Kh; O += Ph*Vh.
// 256 threads, 128 queries/CTA, 64-key double-buffered KV, 2 CTAs/SM.
// SMEM: Qh 0 (34816); stages at 34816 + s*34816 (Kh +0, Vh +17408).
// ---------------------------------------------------------------------------
#define SM_KV  34816
#define STAGE  34816
#define ATTN_SMEM 104448

__device__ __forceinline__ void kv_prefetch(uint32_t dstb, int tid,
    const __half* kh, const __half* vh, int n0)
{
    #pragma unroll
    for (int j = 0; j < 4; j++) {
        int idx = tid + j*256;
        int r = idx >> 4, c = idx & 15;
        CP_ASYNC16(dstb +         r*KROW + c*16, kh + (size_t)(n0 + r)*C_ + c*8);
        CP_ASYNC16(dstb + 17408 + r*KROW + c*16, vh + (size_t)(n0 + r)*C_ + c*8);
    }
}

__global__ __launch_bounds__(256, 2) void attn_mma_kernel()
{
    extern __shared__ char sm[];
    const uint32_t sb = smem_u32(sm);
    const int tid  = threadIdx.x;
    const int lane = tid & 31;
    const int w    = tid >> 5;
    const int b    = blockIdx.y;
    const int q0   = blockIdx.x * 128;
    const int lm8  = lane & 7;
    const int t8   = lane >> 3;

    const __half* qh_b = g_qh + ((size_t)b*N_ + q0)*C_;
    const __half* kh_b = g_kh + (size_t)b*N_*C_;
    const __half* vh_b = g_vh + (size_t)b*N_*C_;

    #pragma unroll
    for (int j = 0; j < 8; j++) {
        int idx = tid + j*256;
        int r = idx >> 4, c = idx & 15;
        CP_ASYNC16(sb + r*KROW + c*16, qh_b + (size_t)r*C_ + c*8);
    }
    kv_prefetch(sb + SM_KV, tid, kh_b, vh_b, 0);
    CP_COMMIT();

    const uint32_t q_addr = sb + (w*16 + (t8&1)*8 + lm8)*KROW + (t8>>1)*16;
    const uint32_t k_off  = ((t8>>1)*8 + lm8)*KROW + (t8&1)*16;
    const uint32_t v_off  = ((t8&1)*8 + lm8)*KROW + (t8>>1)*16;

    float o[16][4];
    #pragma unroll
    for (int f = 0; f < 16; f++) { o[f][0]=0.f; o[f][1]=0.f; o[f][2]=0.f; o[f][3]=0.f; }
    float l0 = 0.f, l1 = 0.f;

    for (int kt = 0; kt < N_/64; kt++) {
        CP_WAIT0();
        __syncthreads();
        if (kt < N_/64 - 1) {
            kv_prefetch(sb + SM_KV + ((kt+1)&1)*STAGE, tid,
                        kh_b, vh_b, (kt+1)*64);
            CP_COMMIT();
        }

        const uint32_t base = sb + SM_KV + (kt&1)*STAGE;
        const uint32_t kbh = base, vbh = base + 17408;

        float s[8][4];
        #pragma unroll
        for (int f = 0; f < 8; f++) { s[f][0]=0.f; s[f][1]=0.f; s[f][2]=0.f; s[f][3]=0.f; }

        #pragma unroll
        for (int ks = 0; ks < 8; ks++) {
            uint32_t qf[4];
            ldsm4(qf, q_addr + ks*32);
            #pragma unroll
            for (int np = 0; np < 4; np++) {
                uint32_t bh[4];
                ldsm4(bh, kbh + k_off + np*16*KROW + ks*32);
                mma16816h(s[2*np],   qf, bh[0], bh[1]);
                mma16816h(s[2*np+1], qf, bh[2], bh[3]);
            }
        }

        #pragma unroll
        for (int ks4 = 0; ks4 < 4; ks4++) {
            uint32_t ah[4];
            #pragma unroll
            for (int fi = 0; fi < 2; fi++) {
                float* sf = s[2*ks4 + fi];
                float e0 = ex2f(sf[0]), e1 = ex2f(sf[1]);
                float e2 = ex2f(sf[2]), e3 = ex2f(sf[3]);
                l0 += e0 + e1;  l1 += e2 + e3;
                ah[fi*2+0] = packhf(e0, e1);
                ah[fi*2+1] = packhf(e2, e3);
            }
            #pragma unroll
            for (int nd = 0; nd < 8; nd++) {
                uint32_t vh[4];
                ldsm4t(vh, vbh + v_off + ks4*16*KROW + nd*32);
                mma16816h(o[2*nd],   ah, vh[0], vh[1]);
                mma16816h(o[2*nd+1], ah, vh[2], vh[3]);
            }
        }
    }

    l0 += __shfl_xor_sync(0xffffffffu, l0, 1);
    l0 += __shfl_xor_sync(0xffffffffu, l0, 2);
    l1 += __shfl_xor_sync(0xffffffffu, l1, 1);
    l1 += __shfl_xor_sync(0xffffffffu, l1, 2);
    const float inv0 = 1.0f / l0, inv1 = 1.0f / l1;

    const int r0 = w*16 + (lane >> 2);
    const int qr = lane & 3;
    #pragma unroll
    for (int nd = 0; nd < 16; nd++) {
        int ch = nd*8 + qr*2;
        float v0 = o[nd][0]*inv0, v1 = o[nd][1]*inv0;
        float v2 = o[nd][2]*inv1, v3 = o[nd][3]*inv1;
        size_t o0 = ((size_t)b*N_ + q0 + r0    )*C_ + ch;
        size_t o1 = ((size_t)b*N_ + q0 + r0 + 8)*C_ + ch;
        uint32_t h01 = packbf(v0, v1), h23 = packbf(v2, v3);
        *(uint32_t*)(g_oh + o0) = h01;
        *(uint32_t*)(g_ol + o0) = packres(v0, v1, h01);
        *(uint32_t*)(g_oh + o1) = h23;
        *(uint32_t*)(g_ol + o1) = packres(v2, v3, h23);
    }
}

// ---------------------------------------------------------------------------
// gemm_out: out[B][C][N] = O(bf16 hi/lo)*Wo^T + bo, 3-term bf16 mma.
// 64-token tiles, 2 CTAs/SM (R14 configuration — frozen).
// ---------------------------------------------------------------------------
#define GO_OL 17408
#define GO_W  34816
#define GO_SMEM 104448

__global__ __launch_bounds__(256, 2) void gemm_out_kernel(
    const float* __restrict__ bo, float* __restrict__ out)
{
    extern __shared__ char sm[];
    const uint32_t sb = smem_u32(sm);
    const int tid  = threadIdx.x;
    const int lane = tid & 31;
    const int w    = tid >> 5;
    const int b    = blockIdx.y;
    const int nt   = blockIdx.x * 64;
    const int lm8  = lane & 7;
    const int t8   = lane >> 3;

    {
        const __nv_bfloat16* oh = g_oh + ((size_t)b*N_ + nt)*C_;
        const __nv_bfloat16* ol = g_ol + ((size_t)b*N_ + nt)*C_;
        const __nv_bfloat16* wh = g_wh + 3*C_*C_;
        const __nv_bfloat16* wl = g_wl + 3*C_*C_;
        #pragma unroll
        for (int j = 0; j < 4; j++) {
            int idx = tid + j*256;
            int r = idx >> 4, c = idx & 15;
            CP_ASYNC16(sb +         r*KROW + c*16, oh + (size_t)r*C_ + c*8);
            CP_ASYNC16(sb + GO_OL + r*KROW + c*16, ol + (size_t)r*C_ + c*8);
        }
        #pragma unroll
        for (int j = 0; j < 8; j++) {
            int idx = tid + j*256;
            int r = idx >> 4, c = idx & 15;
            CP_ASYNC16(sb + GO_W +         r*KROW + c*16, wh + r*C_ + c*8);
            CP_ASYNC16(sb + GO_W + GO_W  + r*KROW + c*16, wl + r*C_ + c*8);
        }
        CP_COMMIT();
    }
    CP_WAIT0();
    __syncthreads();

    const int tr0 = (w & 3) * 16;
    const int cc0 = (w >> 2) * 64;
    const uint32_t a_addr = sb + (tr0 + (t8&1)*8 + lm8)*KROW + (t8>>1)*16;
    const uint32_t b_off  = ((t8>>1)*8 + lm8)*KROW + (t8&1)*16;
    const int r0 = tr0 + (lane >> 2);
    const int qr = lane & 3;

    uint32_t aH[8][4], aL[8][4];
    #pragma unroll
    for (int ks = 0; ks < 8; ks++) {
        ldsm4(aH[ks], a_addr + ks*32);
        ldsm4(aL[ks], a_addr + GO_OL + ks*32);
    }
    __syncthreads();

    float* smT = (float*)sm;                 // [128 ch][68 tok]
    #pragma unroll
    for (int np = 0; np < 4; np++) {
        float acc[2][4];
        #pragma unroll
        for (int f = 0; f < 2; f++)
            { acc[f][0]=0.f; acc[f][1]=0.f; acc[f][2]=0.f; acc[f][3]=0.f; }
        #pragma unroll
        for (int ks = 0; ks < 8; ks++) {
            uint32_t bh[4], bl[4];
            uint32_t ba = b_off + (cc0 + np*16)*KROW + ks*32;
            ldsm4(bh, sb + GO_W + ba);
            ldsm4(bl, sb + GO_W + GO_W + ba);
            mma16816(acc[0], aH[ks], bh[0], bh[1]);
            mma16816(acc[0], aH[ks], bl[0], bl[1]);
            mma16816(acc[0], aL[ks], bh[0], bh[1]);
            mma16816(acc[1], aH[ks], bh[2], bh[3]);
            mma16816(acc[1], aH[ks], bl[2], bl[3]);
            mma16816(acc[1], aL[ks], bh[2], bh[3]);
        }
        #pragma unroll
        for (int f = 0; f < 2; f++) {
            int ch = cc0 + (2*np + f)*8 + qr*2;
            float b0 = __ldg(&bo[ch]), b1 = __ldg(&bo[ch+1]);
            smT[(ch  )*68 + r0    ] = acc[f][0] + b0;
            smT[(ch+1)*68 + r0    ] = acc[f][1] + b1;
            smT[(ch  )*68 + r0 + 8] = acc[f][2] + b0;
            smT[(ch+1)*68 + r0 + 8] = acc[f][3] + b1;
        }
    }
    __syncthreads();

    for (int e = tid; e < 2048; e += 256) {
        int ch = e >> 4, t4 = e & 15;
        float4 v = *(float4*)&smT[ch*68 + t4*4];
        *(float4*)(out + ((size_t)b*C_ + ch)*N_ + nt + t4*4) = v;
    }
}

// ---------------------------------------------------------------------------
extern "C" void kernel_launch(void* const* d_in, const int* in_sizes, int n_in,
                              void* d_out, int out_size)
{
    const float* x  = (const float*)d_in[0];
    const float* fw = (const float*)d_in[1];
    const float* wq = (const float*)d_in[2];
    const float* bq = (const float*)d_in[3];
    const float* wk = (const float*)d_in[4];
    const float* bk = (const float*)d_in[5];
    const float* wv = (const float*)d_in[6];
    const float* bv = (const float*)d_in[7];
    const float* wo = (const float*)d_in[8];
    const float* bo = (const float*)d_in[9];
    float* out = (float*)d_out;

    cudaFuncSetAttribute(gemm_qkv_kernel, cudaFuncAttributeMaxDynamicSharedMemorySize, GQ_SMEM);
    cudaFuncSetAttribute(attn_mma_kernel, cudaFuncAttributeMaxDynamicSharedMemorySize, ATTN_SMEM);
    cudaFuncSetAttribute(gemm_out_kernel, cudaFuncAttributeMaxDynamicSharedMemorySize, GO_SMEM);

    convert_w_kernel<<<32, 256>>>(wq, wk, wv, wo);
    dim3 cg(N_/128, B_);
    gemm_qkv_kernel<<<cg, 256, GQ_SMEM>>>(x, fw, bq, bk, bv);
    attn_mma_kernel<<<cg, 256, ATTN_SMEM>>>();
    dim3 og(N_/64, B_);
    gemm_out_kernel<<<og, 256, GO_SMEM>>>(bo, out);
}

// round 17
// speedup vs baseline: 1.5494x; 1.0069x over previous
#include <cuda_runtime.h>
#include <cuda_bf16.h>
#include <cuda_fp16.h>
#include <stdint.h>

#define B_ 8
#define C_ 128
#define N_ 4096

// ---------------------------------------------------------------------------
// Scratch.
// g_wh/g_wl : weights bf16 hi/lo [4][128][128]
// g_qh/g_kh/g_vh : Q (QSCALE folded), K, V single fp16 [B][N][C]
// g_oh/g_ol : attention output bf16 hi/lo [B][N][C]
// ---------------------------------------------------------------------------
__device__ __nv_bfloat16 g_wh[4*C_*C_];
__device__ __nv_bfloat16 g_wl[4*C_*C_];
__device__ __half        g_qh[B_*N_*C_];
__device__ __half        g_kh[B_*N_*C_];
__device__ __half        g_vh[B_*N_*C_];
__device__ __nv_bfloat16 g_oh[B_*N_*C_];
__device__ __nv_bfloat16 g_ol[B_*N_*C_];

#define QSCALE (0.08838834764831845f * 1.4426950408889634f)

// ---------------------------------------------------------------------------
// PTX helpers
// ---------------------------------------------------------------------------
__device__ __forceinline__ uint32_t smem_u32(const void* p) {
    uint32_t a;
    asm("{ .reg .u64 t; cvta.to.shared.u64 t, %1; cvt.u32.u64 %0, t; }" : "=r"(a) : "l"(p));
    return a;
}
__device__ __forceinline__ void ldsm4(uint32_t* r, uint32_t a) {
    asm volatile("ldmatrix.sync.aligned.m8n8.x4.shared.b16 {%0,%1,%2,%3}, [%4];"
        : "=r"(r[0]), "=r"(r[1]), "=r"(r[2]), "=r"(r[3]) : "r"(a));
}
__device__ __forceinline__ void ldsm4t(uint32_t* r, uint32_t a) {
    asm volatile("ldmatrix.sync.aligned.m8n8.x4.trans.shared.b16 {%0,%1,%2,%3}, [%4];"
        : "=r"(r[0]), "=r"(r[1]), "=r"(r[2]), "=r"(r[3]) : "r"(a));
}
__device__ __forceinline__ void mma16816(float* c, const uint32_t* a,
                                         uint32_t b0, uint32_t b1) {
    asm volatile("mma.sync.aligned.m16n8k16.row.col.f32.bf16.bf16.f32 "
        "{%0,%1,%2,%3}, {%4,%5,%6,%7}, {%8,%9}, {%0,%1,%2,%3};"
        : "+f"(c[0]), "+f"(c[1]), "+f"(c[2]), "+f"(c[3])
        : "r"(a[0]), "r"(a[1]), "r"(a[2]), "r"(a[3]), "r"(b0), "r"(b1));
}
__device__ __forceinline__ void mma16816h(float* c, const uint32_t* a,
                                          uint32_t b0, uint32_t b1) {
    asm volatile("mma.sync.aligned.m16n8k16.row.col.f32.f16.f16.f32 "
        "{%0,%1,%2,%3}, {%4,%5,%6,%7}, {%8,%9}, {%0,%1,%2,%3};"
        : "+f"(c[0]), "+f"(c[1]), "+f"(c[2]), "+f"(c[3])
        : "r"(a[0]), "r"(a[1]), "r"(a[2]), "r"(a[3]), "r"(b0), "r"(b1));
}
__device__ __forceinline__ uint32_t packbf(float lo, float hi) {
    uint32_t r;
    asm("cvt.rn.bf16x2.f32 %0, %1, %2;" : "=r"(r) : "f"(hi), "f"(lo));
    return r;
}
__device__ __forceinline__ uint32_t packhf(float lo, float hi) {
    uint32_t r;
    asm("cvt.rn.f16x2.f32 %0, %1, %2;" : "=r"(r) : "f"(hi), "f"(lo));
    return r;
}
__device__ __forceinline__ uint32_t packres(float v0, float v1, uint32_t h) {
    float h0 = __uint_as_float(h << 16);
    float h1 = __uint_as_float(h & 0xffff0000u);
    return packbf(v0 - h0, v1 - h1);
}
__device__ __forceinline__ float ex2f(float x) {
    float y; asm("ex2.approx.ftz.f32 %0, %1;" : "=f"(y) : "f"(x)); return y;
}
#define CP_ASYNC16(d, g) \
    asm volatile("cp.async.cg.shared.global [%0], [%1], 16;" :: "r"(d), "l"(g) : "memory")
#define CP_COMMIT()  asm volatile("cp.async.commit_group;" ::: "memory")
#define CP_WAIT1()   asm volatile("cp.async.wait_group 1;" ::: "memory")
#define CP_WAIT0()   asm volatile("cp.async.wait_group 0;" ::: "memory")

#define KROW 272

// ---------------------------------------------------------------------------
// convert_w: wq/wk/wv/wo fp32 -> bf16 hi/lo. Grid 32 (8 chunks per matrix).
// ---------------------------------------------------------------------------
__global__ __launch_bounds__(256) void convert_w_kernel(
    const float* __restrict__ wq, const float* __restrict__ wk,
    const float* __restrict__ wv, const float* __restrict__ wo)
{
    const float* src[4] = {wq, wk, wv, wo};
    const int m = blockIdx.x >> 3;
    const int ch = blockIdx.x & 7;
    const float* s = src[m] + ch * (C_*C_/8);
    __nv_bfloat16* dh = g_wh + m*C_*C_ + ch*(C_*C_/8);
    __nv_bfloat16* dl = g_wl + m*C_*C_ + ch*(C_*C_/8);
    for (int e = threadIdx.x; e < C_*C_/16; e += 256) {
        float v0 = s[2*e], v1 = s[2*e+1];
        uint32_t h = packbf(v0, v1);
        *(uint32_t*)(dh + 2*e) = h;
        *(uint32_t*)(dl + 2*e) = packres(v0, v1, h);
    }
}

// ---------------------------------------------------------------------------
// gemm_qkv (convert_x fused, 64-token x 64-channel tiles, 2 CTAs/SM,
// HALF-WIDTH double-buffered W pipeline with early W0 prefetch):
// Grid (N/64, 2 ch-halves, B). Each CTA converts its 64-token X tile
// (duplicated across halves; cheap) then runs 3 projections over its
// 64 output channels with the R16 group-A/B/C wait chain at half W size.
// SMEM: Xh 0 (64x272=17408), Xl 17408; W buf0 34816 (Wh +0, Wl +17408),
//       W buf1 69632 (Wh +0, Wl +17408). Total 104448 -> 2 CTAs/SM.
// fp32 X staging [128c][68n] = 34816 B occupies buf0 during the convert;
// W0 prefetches into buf1 concurrently.
// Warp w: tokens (w&3)*16, channel quarter (w>>2)*32 (np loop = 2).
// ---------------------------------------------------------------------------
#define GQ_XL 17408
#define GQ_W  34816
#define GQ_WL 17408
#define GQ_WS 34816
#define GQ_SMEM 104448

__device__ __forceinline__ void stage_w_half(uint32_t dst, int tid, int p, int half) {
    const __nv_bfloat16* sh = g_wh + p*C_*C_ + half*64*C_;
    const __nv_bfloat16* sl = g_wl + p*C_*C_ + half*64*C_;
    #pragma unroll
    for (int j = 0; j < 4; j++) {
        int idx = tid + j*256;               // 0..1023: 64 rows x 16 chunks
        int r = idx >> 4, c = idx & 15;
        CP_ASYNC16(dst +         r*KROW + c*16, sh + r*C_ + c*8);
        CP_ASYNC16(dst + GQ_WL + r*KROW + c*16, sl + r*C_ + c*8);
    }
}

__global__ __launch_bounds__(256, 2) void gemm_qkv_kernel(
    const float* __restrict__ X, const float* __restrict__ fw,
    const float* __restrict__ bq, const float* __restrict__ bk,
    const float* __restrict__ bv)
{
    extern __shared__ char sm[];
    const uint32_t sb = smem_u32(sm);
    const int tid  = threadIdx.x;
    const int lane = tid & 31;
    const int w    = tid >> 5;
    const int half = blockIdx.y;
    const int b    = blockIdx.z;
    const int nt   = blockIdx.x * 64;
    const int lm8  = lane & 7;
    const int t8   = lane >> 3;

    // early prefetch: W0-half -> buf1 (group A), overlaps with convert below
    stage_w_half(sb + GQ_W + GQ_WS, tid, 0, half);
    CP_COMMIT();

    // ---- fused convert_x: fp32 stage (buf0 region) -> transpose -> bf16 hi/lo
    {
        float* xs = (float*)(sm + GQ_W);      // [c][n] 128x68 fp32 staging
        for (int e = tid; e < C_*64; e += 256) {
            int c = e >> 6, n = e & 63;
            xs[c*68 + n] = X[((size_t)b*C_ + c)*N_ + nt + n] * fw[c];
        }
        __syncthreads();
        for (int e = tid; e < 4096; e += 256) {      // 64 tok x 64 c-pairs
            int n = e >> 6, c2 = e & 63;
            float v0 = xs[(2*c2  )*68 + n];
            float v1 = xs[(2*c2+1)*68 + n];
            uint32_t h = packbf(v0, v1);
            *(uint32_t*)(sm +         n*KROW + c2*4) = h;
            *(uint32_t*)(sm + GQ_XL + n*KROW + c2*4) = packres(v0, v1, h);
        }
        __syncthreads();                      // buf0 free for W1
    }

    // W1-half -> buf0 (group B)
    stage_w_half(sb + GQ_W, tid, 1, half);
    CP_COMMIT();
    CP_WAIT1();                               // W0 (group A) resident
    __syncthreads();

    const int tr0 = (w & 3) * 16;             // token group
    const int cq0 = (w >> 2) * 32;            // channel quarter (local 0/32)
    const uint32_t a_addr = sb + (tr0 + (t8&1)*8 + lm8)*KROW + (t8>>1)*16;
    const uint32_t b_off  = ((t8>>1)*8 + lm8)*KROW + (t8&1)*16;
    const int r0 = tr0 + (lane >> 2);
    const int qr = lane & 3;

    uint32_t aH[8][4], aL[8][4];
    #pragma unroll
    for (int ks = 0; ks < 8; ks++) {
        ldsm4(aH[ks], a_addr + ks*32);
        ldsm4(aL[ks], a_addr + GQ_XL + ks*32);
    }

    const float* Bp[3] = {bq, bk, bv};

    for (int p = 0; p < 3; p++) {
        // p=0: buf1 (W0); p=1: buf0 (W1); p=2: buf1 (W2 restaged)
        const uint32_t wb = sb + GQ_W + ((p & 1) ^ 1) * GQ_WS;
        const float* bias = Bp[p];
        __half* dst = (p == 0) ? g_qh : ((p == 1) ? g_kh : g_vh);
        const float sc = (p == 0) ? QSCALE : 1.0f;
        #pragma unroll
        for (int np = 0; np < 2; np++) {
            float acc[2][4];
            #pragma unroll
            for (int f = 0; f < 2; f++)
                { acc[f][0]=0.f; acc[f][1]=0.f; acc[f][2]=0.f; acc[f][3]=0.f; }
            #pragma unroll
            for (int ks = 0; ks < 8; ks++) {
                uint32_t bh[4], bl[4];
                uint32_t ba = b_off + (cq0 + np*16)*KROW + ks*32;
                ldsm4(bh, wb + ba);
                ldsm4(bl, wb + GQ_WL + ba);
                mma16816(acc[0], aH[ks], bh[0], bh[1]);
                mma16816(acc[0], aH[ks], bl[0], bl[1]);
                mma16816(acc[0], aL[ks], bh[0], bh[1]);
                mma16816(acc[1], aH[ks], bh[2], bh[3]);
                mma16816(acc[1], aH[ks], bl[2], bl[3]);
                mma16816(acc[1], aL[ks], bh[2], bh[3]);
            }
            #pragma unroll
            for (int f = 0; f < 2; f++) {
                int ch = half*64 + cq0 + (2*np + f)*8 + qr*2;
                float b0 = __ldg(&bias[ch]), b1 = __ldg(&bias[ch+1]);
                float v0 = (acc[f][0] + b0)*sc, v1 = (acc[f][1] + b1)*sc;
                float v2 = (acc[f][2] + b0)*sc, v3 = (acc[f][3] + b1)*sc;
                size_t o0 = ((size_t)b*N_ + nt + r0    )*C_ + ch;
                size_t o1 = ((size_t)b*N_ + nt + r0 + 8)*C_ + ch;
                *(uint32_t*)(dst + o0) = packhf(v0, v1);
                *(uint32_t*)(dst + o1) = packhf(v2, v3);
            }
        }
        if (p == 0) {
            __syncthreads();                  // all warps done reading buf1
            stage_w_half(sb + GQ_W + GQ_WS, tid, 2, half);   // W2 -> buf1 (C)
            CP_COMMIT();
            CP_WAIT1();                       // W1 (group B) resident
            __syncthreads();
        } else if (p == 1) {
            CP_WAIT0();                       // W2 resident
            __syncthreads();
        }
    }
}

// ---------------------------------------------------------------------------
// fp16 mma flash attention (R12 configuration — frozen): S = Qh*Kh; O += Ph*Vh.
// 256 threads, 128 queries/CTA, 64-key double-buffered KV, 2 CTAs/SM.
// SMEM: Qh 0 (34816); stages at 34816 + s*34816 (Kh +0, Vh +17408).
// ---------------------------------------------------------------------------
#define SM_KV  34816
#define STAGE  34816
#define ATTN_SMEM 104448

__device__ __forceinline__ void kv_prefetch(uint32_t dstb, int tid,
    const __half* kh, const __half* vh, int n0)
{
    #pragma unroll
    for (int j = 0; j < 4; j++) {
        int idx = tid + j*256;
        int r = idx >> 4, c = idx & 15;
        CP_ASYNC16(dstb +         r*KROW + c*16, kh + (size_t)(n0 + r)*C_ + c*8);
        CP_ASYNC16(dstb + 17408 + r*KROW + c*16, vh + (size_t)(n0 + r)*C_ + c*8);
    }
}

__global__ __launch_bounds__(256, 2) void attn_mma_kernel()
{
    extern __shared__ char sm[];
    const uint32_t sb = smem_u32(sm);
    const int tid  = threadIdx.x;
    const int lane = tid & 31;
    const int w    = tid >> 5;
    const int b    = blockIdx.y;
    const int q0   = blockIdx.x * 128;
    const int lm8  = lane & 7;
    const int t8   = lane >> 3;

    const __half* qh_b = g_qh + ((size_t)b*N_ + q0)*C_;
    const __half* kh_b = g_kh + (size_t)b*N_*C_;
    const __half* vh_b = g_vh + (size_t)b*N_*C_;

    #pragma unroll
    for (int j = 0; j < 8; j++) {
        int idx = tid + j*256;
        int r = idx >> 4, c = idx & 15;
        CP_ASYNC16(sb + r*KROW + c*16, qh_b + (size_t)r*C_ + c*8);
    }
    kv_prefetch(sb + SM_KV, tid, kh_b, vh_b, 0);
    CP_COMMIT();

    const uint32_t q_addr = sb + (w*16 + (t8&1)*8 + lm8)*KROW + (t8>>1)*16;
    const uint32_t k_off  = ((t8>>1)*8 + lm8)*KROW + (t8&1)*16;
    const uint32_t v_off  = ((t8&1)*8 + lm8)*KROW + (t8>>1)*16;

    float o[16][4];
    #pragma unroll
    for (int f = 0; f < 16; f++) { o[f][0]=0.f; o[f][1]=0.f; o[f][2]=0.f; o[f][3]=0.f; }
    float l0 = 0.f, l1 = 0.f;

    for (int kt = 0; kt < N_/64; kt++) {
        CP_WAIT0();
        __syncthreads();
        if (kt < N_/64 - 1) {
            kv_prefetch(sb + SM_KV + ((kt+1)&1)*STAGE, tid,
                        kh_b, vh_b, (kt+1)*64);
            CP_COMMIT();
        }

        const uint32_t base = sb + SM_KV + (kt&1)*STAGE;
        const uint32_t kbh = base, vbh = base + 17408;

        float s[8][4];
        #pragma unroll
        for (int f = 0; f < 8; f++) { s[f][0]=0.f; s[f][1]=0.f; s[f][2]=0.f; s[f][3]=0.f; }

        #pragma unroll
        for (int ks = 0; ks < 8; ks++) {
            uint32_t qf[4];
            ldsm4(qf, q_addr + ks*32);
            #pragma unroll
            for (int np = 0; np < 4; np++) {
                uint32_t bh[4];
                ldsm4(bh, kbh + k_off + np*16*KROW + ks*32);
                mma16816h(s[2*np],   qf, bh[0], bh[1]);
                mma16816h(s[2*np+1], qf, bh[2], bh[3]);
            }
        }

        #pragma unroll
        for (int ks4 = 0; ks4 < 4; ks4++) {
            uint32_t ah[4];
            #pragma unroll
            for (int fi = 0; fi < 2; fi++) {
                float* sf = s[2*ks4 + fi];
                float e0 = ex2f(sf[0]), e1 = ex2f(sf[1]);
                float e2 = ex2f(sf[2]), e3 = ex2f(sf[3]);
                l0 += e0 + e1;  l1 += e2 + e3;
                ah[fi*2+0] = packhf(e0, e1);
                ah[fi*2+1] = packhf(e2, e3);
            }
            #pragma unroll
            for (int nd = 0; nd < 8; nd++) {
                uint32_t vh[4];
                ldsm4t(vh, vbh + v_off + ks4*16*KROW + nd*32);
                mma16816h(o[2*nd],   ah, vh[0], vh[1]);
                mma16816h(o[2*nd+1], ah, vh[2], vh[3]);
            }
        }
    }

    l0 += __shfl_xor_sync(0xffffffffu, l0, 1);
    l0 += __shfl_xor_sync(0xffffffffu, l0, 2);
    l1 += __shfl_xor_sync(0xffffffffu, l1, 1);
    l1 += __shfl_xor_sync(0xffffffffu, l1, 2);
    const float inv0 = 1.0f / l0, inv1 = 1.0f / l1;

    const int r0 = w*16 + (lane >> 2);
    const int qr = lane & 3;
    #pragma unroll
    for (int nd = 0; nd < 16; nd++) {
        int ch = nd*8 + qr*2;
        float v0 = o[nd][0]*inv0, v1 = o[nd][1]*inv0;
        float v2 = o[nd][2]*inv1, v3 = o[nd][3]*inv1;
        size_t o0 = ((size_t)b*N_ + q0 + r0    )*C_ + ch;
        size_t o1 = ((size_t)b*N_ + q0 + r0 + 8)*C_ + ch;
        uint32_t h01 = packbf(v0, v1), h23 = packbf(v2, v3);
        *(uint32_t*)(g_oh + o0) = h01;
        *(uint32_t*)(g_ol + o0) = packres(v0, v1, h01);
        *(uint32_t*)(g_oh + o1) = h23;
        *(uint32_t*)(g_ol + o1) = packres(v2, v3, h23);
    }
}

// ---------------------------------------------------------------------------
// gemm_out: out[B][C][N] = O(bf16 hi/lo)*Wo^T + bo, 3-term bf16 mma.
// 64-token tiles, 2 CTAs/SM (R14 configuration — frozen).
// ---------------------------------------------------------------------------
#define GO_OL 17408
#define GO_W  34816
#define GO_SMEM 104448

__global__ __launch_bounds__(256, 2) void gemm_out_kernel(
    const float* __restrict__ bo, float* __restrict__ out)
{
    extern __shared__ char sm[];
    const uint32_t sb = smem_u32(sm);
    const int tid  = threadIdx.x;
    const int lane = tid & 31;
    const int w    = tid >> 5;
    const int b    = blockIdx.y;
    const int nt   = blockIdx.x * 64;
    const int lm8  = lane & 7;
    const int t8   = lane >> 3;

    {
        const __nv_bfloat16* oh = g_oh + ((size_t)b*N_ + nt)*C_;
        const __nv_bfloat16* ol = g_ol + ((size_t)b*N_ + nt)*C_;
        const __nv_bfloat16* wh = g_wh + 3*C_*C_;
        const __nv_bfloat16* wl = g_wl + 3*C_*C_;
        #pragma unroll
        for (int j = 0; j < 4; j++) {
            int idx = tid + j*256;
            int r = idx >> 4, c = idx & 15;
            CP_ASYNC16(sb +         r*KROW + c*16, oh + (size_t)r*C_ + c*8);
            CP_ASYNC16(sb + GO_OL + r*KROW + c*16, ol + (size_t)r*C_ + c*8);
        }
        #pragma unroll
        for (int j = 0; j < 8; j++) {
            int idx = tid + j*256;
            int r = idx >> 4, c = idx & 15;
            CP_ASYNC16(sb + GO_W +         r*KROW + c*16, wh + r*C_ + c*8);
            CP_ASYNC16(sb + GO_W + GO_W  + r*KROW + c*16, wl + r*C_ + c*8);
        }
        CP_COMMIT();
    }
    CP_WAIT0();
    __syncthreads();

    const int tr0 = (w & 3) * 16;
    const int cc0 = (w >> 2) * 64;
    const uint32_t a_addr = sb + (tr0 + (t8&1)*8 + lm8)*KROW + (t8>>1)*16;
    const uint32_t b_off  = ((t8>>1)*8 + lm8)*KROW + (t8&1)*16;
    const int r0 = tr0 + (lane >> 2);
    const int qr = lane & 3;

    uint32_t aH[8][4], aL[8][4];
    #pragma unroll
    for (int ks = 0; ks < 8; ks++) {
        ldsm4(aH[ks], a_addr + ks*32);
        ldsm4(aL[ks], a_addr + GO_OL + ks*32);
    }
    __syncthreads();

    float* smT = (float*)sm;                 // [128 ch][68 tok]
    #pragma unroll
    for (int np = 0; np < 4; np++) {
        float acc[2][4];
        #pragma unroll
        for (int f = 0; f < 2; f++)
            { acc[f][0]=0.f; acc[f][1]=0.f; acc[f][2]=0.f; acc[f][3]=0.f; }
        #pragma unroll
        for (int ks = 0; ks < 8; ks++) {
            uint32_t bh[4], bl[4];
            uint32_t ba = b_off + (cc0 + np*16)*KROW + ks*32;
            ldsm4(bh, sb + GO_W + ba);
            ldsm4(bl, sb + GO_W + GO_W + ba);
            mma16816(acc[0], aH[ks], bh[0], bh[1]);
            mma16816(acc[0], aH[ks], bl[0], bl[1]);
            mma16816(acc[0], aL[ks], bh[0], bh[1]);
            mma16816(acc[1], aH[ks], bh[2], bh[3]);
            mma16816(acc[1], aH[ks], bl[2], bl[3]);
            mma16816(acc[1], aL[ks], bh[2], bh[3]);
        }
        #pragma unroll
        for (int f = 0; f < 2; f++) {
            int ch = cc0 + (2*np + f)*8 + qr*2;
            float b0 = __ldg(&bo[ch]), b1 = __ldg(&bo[ch+1]);
            smT[(ch  )*68 + r0    ] = acc[f][0] + b0;
            smT[(ch+1)*68 + r0    ] = acc[f][1] + b1;
            smT[(ch  )*68 + r0 + 8] = acc[f][2] + b0;
            smT[(ch+1)*68 + r0 + 8] = acc[f][3] + b1;
        }
    }
    __syncthreads();

    for (int e = tid; e < 2048; e += 256) {
        int ch = e >> 4, t4 = e & 15;
        float4 v = *(float4*)&smT[ch*68 + t4*4];
        *(float4*)(out + ((size_t)b*C_ + ch)*N_ + nt + t4*4) = v;
    }
}

// ---------------------------------------------------------------------------
extern "C" void kernel_launch(void* const* d_in, const int* in_sizes, int n_in,
                              void* d_out, int out_size)
{
    const float* x  = (const float*)d_in[0];
    const float* fw = (const float*)d_in[1];
    const float* wq = (const float*)d_in[2];
    const float* bq = (const float*)d_in[3];
    const float* wk = (const float*)d_in[4];
    const float* bk = (const float*)d_in[5];
    const float* wv = (const float*)d_in[6];
    const float* bv = (const float*)d_in[7];
    const float* wo = (const float*)d_in[8];
    const float* bo = (const float*)d_in[9];
    float* out = (float*)d_out;

    cudaFuncSetAttribute(gemm_qkv_kernel, cudaFuncAttributeMaxDynamicSharedMemorySize, GQ_SMEM);
    cudaFuncSetAttribute(attn_mma_kernel, cudaFuncAttributeMaxDynamicSharedMemorySize, ATTN_SMEM);
    cudaFuncSetAttribute(gemm_out_kernel, cudaFuncAttributeMaxDynamicSharedMemorySize, GO_SMEM);

    convert_w_kernel<<<32, 256>>>(wq, wk, wv, wo);
    dim3 qg(N_/64, 2, B_);
    gemm_qkv_kernel<<<qg, 256, GQ_SMEM>>>(x, fw, bq, bk, bv);
    dim3 ag(N_/128, B_);
    attn_mma_kernel<<<ag, 256, ATTN_SMEM>>>();
    dim3 og(N_/64, B_);
    gemm_out_kernel<<<og, 256, GO_SMEM>>>(bo, out);
}